// round 14
// baseline (speedup 1.0000x reference)
#include <cuda_runtime.h>
#include <cuda_bf16.h>

// ----------------------------------------------------------------------------
// SplineCoupling fused kernel, round 14: warp-specialized phase 3.
//  - prep kernel pre-splits Wp into bf16 hi/lo (device globals, zero-padded)
//  - phase 3: warps 0-7 GEMM (mma.sync bf16 2-term split) -> raw (2x64-row
//    buffers); warps 8-15 run the spline epilogue; named-barrier pipeline.
//  - phases 1-2 FFMA as proven (H1 un-aliased from xm).
// ----------------------------------------------------------------------------

namespace {
constexpr int kB       = 262144;
constexpr int kThreads = 512;

// byte offsets in dynamic smem
constexpr int XU_B   = 0;         // 16896 : xu -> yu (128*33 f32)
constexpr int BP_B   = 16896;     // 3200  : bp
constexpr int BV_B   = 20096;     // 3072  : b0,g0,be0,b1,g1,be1
constexpr int AHI_B  = 23168;     // 34816 : A_hi bf16 [m][k] stride 272B
constexpr int ALO_B  = 57984;     // 34816 : A_lo
constexpr int BHI_B  = 92800;     // 26624 : B_hi bf16 [k][104] stride 208B
constexpr int BLO_B  = 119424;    // 26624 : B_lo
constexpr int RAW_B  = 146048;    // 2 x 26880 : raw f32 [64][105], double buf
constexpr int SMEM_BYTES = 199808;
// phase 1-2 overlays
constexpr int W_B  = AHI_B;       // W0 (16KB) then W1 (64KB) fp32
constexpr int XM_B = BHI_B;       // xm 128*33 f32
constexpr int H1_B = 109696;      // H1 128*129 f32 (no aliasing with xm)
}  // namespace

__device__ __align__(16) __nv_bfloat16 gWpHi[8 * 128 * 104];
__device__ __align__(16) __nv_bfloat16 gWpLo[8 * 128 * 104];

__global__ void prep_wp_kernel(const float* __restrict__ Wp) {
    int idx = blockIdx.x * blockDim.x + threadIdx.x;
    if (idx >= 8 * 128 * 104) return;
    int c = idx / (128 * 104);
    int rem = idx - c * 128 * 104;
    int k = rem / 104, n = rem - k * 104;
    float v = (n < 100) ? Wp[k * 800 + c * 100 + n] : 0.f;
    __nv_bfloat16 hi = __float2bfloat16(v);
    __nv_bfloat16 lo = __float2bfloat16(v - __bfloat162float(hi));
    gWpHi[idx] = hi;
    gWpLo[idx] = lo;
}

__device__ __forceinline__ void cp_async16(unsigned dst, const void* src) {
    asm volatile("cp.async.cg.shared.global [%0], [%1], 16;" :: "r"(dst), "l"(src));
}
__device__ __forceinline__ void cp_commit() { asm volatile("cp.async.commit_group;"); }
__device__ __forceinline__ void cp_wait0()  { asm volatile("cp.async.wait_group 0;"); }

__device__ __forceinline__ void bar_arrive512(int id) {
    asm volatile("bar.arrive %0, 512;" :: "r"(id));
}
__device__ __forceinline__ void bar_sync_cnt(int id, int n) {
    asm volatile("bar.sync %0, %1;" :: "r"(id), "r"(n));
}

__device__ __forceinline__ void ldsm_x4(unsigned addr, unsigned& r0, unsigned& r1,
                                        unsigned& r2, unsigned& r3) {
    asm volatile("ldmatrix.sync.aligned.m8n8.x4.shared.b16 {%0,%1,%2,%3}, [%4];"
                 : "=r"(r0), "=r"(r1), "=r"(r2), "=r"(r3) : "r"(addr));
}
__device__ __forceinline__ void ldsm_x2t(unsigned addr, unsigned& r0, unsigned& r1) {
    asm volatile("ldmatrix.sync.aligned.m8n8.x2.trans.shared.b16 {%0,%1}, [%2];"
                 : "=r"(r0), "=r"(r1) : "r"(addr));
}
__device__ __forceinline__ void mma16816(float* d, const unsigned* a,
                                         unsigned b0, unsigned b1) {
    asm volatile(
        "mma.sync.aligned.m16n8k16.row.col.f32.bf16.bf16.f32 "
        "{%0,%1,%2,%3}, {%4,%5,%6,%7}, {%8,%9}, {%0,%1,%2,%3};"
        : "+f"(d[0]), "+f"(d[1]), "+f"(d[2]), "+f"(d[3])
        : "r"(a[0]), "r"(a[1]), "r"(a[2]), "r"(a[3]), "r"(b0), "r"(b1));
}

// RQS spline epilogue for one (row, dim): proven numerics since R6.
__device__ __forceinline__ float rqs_epilogue(const float* __restrict__ rawp,
                                              const float* __restrict__ bpd,
                                              float* __restrict__ xuslot)
{
    float wr[8], hr[8], dr9[9];
    #pragma unroll
    for (int j = 0; j < 8; j++) wr[j] = rawp[j] + bpd[j];
    #pragma unroll
    for (int j = 0; j < 8; j++) hr[j] = rawp[8 + j] + bpd[8 + j];
    #pragma unroll
    for (int j = 0; j < 9; j++) dr9[j] = rawp[16 + j] + bpd[16 + j];

    float mw = wr[0];
    #pragma unroll
    for (int j = 1; j < 8; j++) mw = fmaxf(mw, wr[j]);
    float ew[8], sw = 0.f;
    #pragma unroll
    for (int j = 0; j < 8; j++) { ew[j] = __expf(wr[j] - mw); sw += ew[j]; }
    float scw = 5.952f / sw;
    float w[8];
    #pragma unroll
    for (int j = 0; j < 8; j++) w[j] = 0.006f + ew[j] * scw;

    float mh = hr[0];
    #pragma unroll
    for (int j = 1; j < 8; j++) mh = fmaxf(mh, hr[j]);
    float eh[8], shs = 0.f;
    #pragma unroll
    for (int j = 0; j < 8; j++) { eh[j] = __expf(hr[j] - mh); shs += eh[j]; }
    float sch = 5.952f / shs;
    float h[8];
    #pragma unroll
    for (int j = 0; j < 8; j++) h[j] = 0.006f + eh[j] * sch;

    float dv[9];
    #pragma unroll
    for (int j = 0; j < 9; j++) {
        float xx = dr9[j];
        dv[j] = fmaxf(xx, 0.f) + __logf(1.f + __expf(-fabsf(xx))) + 0.001f;
    }

    float xu = *xuslot;
    bool inside = (xu > -3.f) && (xu < 3.f);
    float xc = fminf(fmaxf(xu, -3.f), 3.f);

    float cwv[9], chv[9];
    cwv[0] = -3.f; chv[0] = -3.f;
    #pragma unroll
    for (int j = 0; j < 8; j++) {
        cwv[j + 1] = cwv[j] + w[j];
        chv[j + 1] = chv[j] + h[j];
    }
    int idx = 0;
    #pragma unroll
    for (int j = 1; j <= 8; j++) idx += (xc >= cwv[j]) ? 1 : 0;
    idx = min(idx, 7);

    float w_k = w[0], x_k = cwv[0], h_k = h[0], y_k = chv[0];
    float d_k = dv[0], d_k1 = dv[1];
    #pragma unroll
    for (int j = 1; j < 8; j++) {
        if (idx == j) {
            w_k = w[j]; x_k = cwv[j]; h_k = h[j]; y_k = chv[j];
            d_k = dv[j]; d_k1 = dv[j + 1];
        }
    }
    float s   = h_k / w_k;
    float th  = (xc - x_k) / w_k;
    float om  = 1.f - th;
    float t1m = th * om;
    float den = s + (d_k1 + d_k - 2.f * s) * t1m;
    float yin = y_k + h_k * (s * th * th + d_k * t1m) / den;
    float num = d_k1 * th * th + 2.f * s * t1m + d_k * om * om;
    float ldin = 2.f * __logf(s) + __logf(num) - 2.f * __logf(den);

    *xuslot = inside ? yin : xu;
    return inside ? ldin : 0.f;
}

__global__ void __launch_bounds__(512, 1) spline_fused_kernel(
    const float* __restrict__ x,
    const float* __restrict__ W0, const float* __restrict__ b0,
    const float* __restrict__ g0, const float* __restrict__ be0,
    const float* __restrict__ W1, const float* __restrict__ b1,
    const float* __restrict__ g1, const float* __restrict__ be1,
    const float* __restrict__ Wp, const float* __restrict__ bp,
    float* __restrict__ out)
{
    extern __shared__ char smc[];
    float* sXU  = reinterpret_cast<float*>(smc + XU_B);
    float* sBP  = reinterpret_cast<float*>(smc + BP_B);
    float* sBV  = reinterpret_cast<float*>(smc + BV_B);
    float* sW   = reinterpret_cast<float*>(smc + W_B);    // W0 -> W1 (fp32)
    float* sXM  = reinterpret_cast<float*>(smc + XM_B);   // xm
    float* sH1  = reinterpret_cast<float*>(smc + H1_B);   // H1
    const unsigned smem_u32 = (unsigned)__cvta_generic_to_shared(smc);

    const int tid  = threadIdx.x;
    const int wid  = tid >> 5;
    const int lane = tid & 31;
    const int r0   = blockIdx.x * 128;

    // ---------------- cooperative loads ----------------
    {
        const float4* xg = reinterpret_cast<const float4*>(x + (size_t)r0 * 64);
        #pragma unroll
        for (int i = tid; i < 128 * 16; i += kThreads) {
            int r = i >> 4, v = i & 15;
            float4 f = xg[i];
            sXM[r * 33 + 2 * v]     = f.x;
            sXU[r * 33 + 2 * v]     = f.y;
            sXM[r * 33 + 2 * v + 1] = f.z;
            sXU[r * 33 + 2 * v + 1] = f.w;
        }
        const float4* w0g = reinterpret_cast<const float4*>(W0);
        #pragma unroll
        for (int i = tid; i < 1024; i += kThreads)
            reinterpret_cast<float4*>(sW)[i] = w0g[i];
        const float4* bpg = reinterpret_cast<const float4*>(bp);
        #pragma unroll
        for (int i = tid; i < 200; i += kThreads)
            reinterpret_cast<float4*>(sBP)[i] = bpg[i];
        if (tid < 128) {
            sBV[tid]       = b0[tid];
            sBV[128 + tid] = g0[tid];
            sBV[256 + tid] = be0[tid];
            sBV[384 + tid] = b1[tid];
            sBV[512 + tid] = g1[tid];
            sBV[640 + tid] = be1[tid];
        }
    }
    __syncthreads();

    // ---------------- Phase 1: GEMM1 (K=32) tile 4x8 ----------------
    {
        const int rg = tid >> 4, cg = tid & 15;
        float acc1[4][8];
        #pragma unroll
        for (int r = 0; r < 4; r++)
            #pragma unroll
            for (int i = 0; i < 8; i++) acc1[r][i] = 0.f;

        #pragma unroll 4
        for (int k = 0; k < 32; k++) {
            float a[4];
            #pragma unroll
            for (int r = 0; r < 4; r++) a[r] = sXM[(rg * 4 + r) * 33 + k];
            #pragma unroll
            for (int i = 0; i < 8; i++) {
                float b = sW[k * 128 + cg + 16 * i];
                #pragma unroll
                for (int r = 0; r < 4; r++) acc1[r][i] += a[r] * b;
            }
        }
        __syncthreads();   // W0 reads done

        {   // kick W1 into sW via cp.async
            const float4* w1g = reinterpret_cast<const float4*>(W1);
            #pragma unroll
            for (int i = tid; i < 4096; i += kThreads)
                cp_async16(smem_u32 + (unsigned)(W_B + i * 16), w1g + i);
            cp_commit();
        }

        float mu[4], rs[4];
        #pragma unroll
        for (int r = 0; r < 4; r++) {
            float s1 = 0.f, s2 = 0.f;
            #pragma unroll
            for (int i = 0; i < 8; i++) {
                float v = acc1[r][i] + sBV[cg + 16 * i];
                acc1[r][i] = v;
                s1 += v; s2 += v * v;
            }
            #pragma unroll
            for (int d = 1; d < 16; d <<= 1) {
                s1 += __shfl_xor_sync(0xffffffffu, s1, d);
                s2 += __shfl_xor_sync(0xffffffffu, s2, d);
            }
            mu[r] = s1 * (1.f / 128.f);
            rs[r] = rsqrtf(s2 * (1.f / 128.f) - mu[r] * mu[r] + 1e-6f);
        }
        #pragma unroll
        for (int i = 0; i < 8; i++) {
            int c = cg + 16 * i;
            float gg = sBV[128 + c], bb = sBV[256 + c];
            #pragma unroll
            for (int r = 0; r < 4; r++) {
                float h = (acc1[r][i] - mu[r]) * rs[r] * gg + bb;
                sH1[(rg * 4 + r) * 129 + c] = fmaxf(h, 0.f);
            }
        }
    }
    cp_wait0();
    __syncthreads();

    // ---------------- Phase 2: GEMM2 (K=128) tile 8x8, 256 threads ---------
    {
        const bool p2  = tid < 256;
        const int rg2  = tid >> 4;
        const int cg2  = tid & 15;
        float a2[8][8];
        if (p2) {
            #pragma unroll
            for (int r = 0; r < 8; r++)
                #pragma unroll
                for (int j = 0; j < 8; j++) a2[r][j] = 0.f;

            #pragma unroll 2
            for (int k = 0; k < 128; k++) {
                float bv_[8];
                #pragma unroll
                for (int j = 0; j < 8; j++) bv_[j] = sW[k * 128 + 16 * j + cg2];
                #pragma unroll
                for (int r = 0; r < 8; r++) {
                    float av = sH1[(rg2 * 8 + r) * 129 + k];
                    #pragma unroll
                    for (int j = 0; j < 8; j++) a2[r][j] += av * bv_[j];
                }
            }
            #pragma unroll
            for (int r = 0; r < 8; r++) {
                float s1 = 0.f, s2 = 0.f;
                #pragma unroll
                for (int j = 0; j < 8; j++) {
                    float v = a2[r][j] + sBV[384 + 16 * j + cg2];
                    a2[r][j] = v;
                    s1 += v; s2 += v * v;
                }
                #pragma unroll
                for (int d = 1; d < 16; d <<= 1) {
                    s1 += __shfl_xor_sync(0xffffffffu, s1, d);
                    s2 += __shfl_xor_sync(0xffffffffu, s2, d);
                }
                float mu = s1 * (1.f / 128.f);
                float rs = rsqrtf(s2 * (1.f / 128.f) - mu * mu + 1e-6f);
                #pragma unroll
                for (int j = 0; j < 8; j++) {
                    int c = 16 * j + cg2;
                    float h = fmaxf((a2[r][j] - mu) * rs * sBV[512 + c] + sBV[640 + c], 0.f)
                              + sH1[(rg2 * 8 + r) * 129 + c];   // residual
                    a2[r][j] = h;
                }
            }
        }
        __syncthreads();   // all W1 + H1 reads complete (uniform barrier)
        if (p2) {
            // H2 -> A_hi/A_lo bf16, [m][k] row-major stride 272B
            #pragma unroll
            for (int r = 0; r < 8; r++) {
                int m = rg2 * 8 + r;
                #pragma unroll
                for (int j = 0; j < 8; j++) {
                    int k = 16 * j + cg2;
                    float v = a2[r][j];
                    __nv_bfloat16 hi = __float2bfloat16(v);
                    __nv_bfloat16 lo = __float2bfloat16(v - __bfloat162float(hi));
                    *reinterpret_cast<unsigned short*>(smc + AHI_B + m * 272 + k * 2) =
                        __bfloat16_as_ushort(hi);
                    *reinterpret_cast<unsigned short*>(smc + ALO_B + m * 272 + k * 2) =
                        __bfloat16_as_ushort(lo);
                }
            }
        }
    }
    // initial stage of B(0) from pre-split globals (all 512 threads)
    {
        const char* srcH = reinterpret_cast<const char*>(gWpHi);
        const char* srcL = reinterpret_cast<const char*>(gWpLo);
        #pragma unroll
        for (int i = tid; i < 1664; i += kThreads) {
            cp_async16(smem_u32 + (unsigned)(BHI_B + i * 16), srcH + i * 16);
            cp_async16(smem_u32 + (unsigned)(BLO_B + i * 16), srcL + i * 16);
        }
        cp_commit();
        cp_wait0();
    }
    __syncthreads();

    // ---------------- Phase 3: warp-specialized pipeline -------------------
    // barriers: full0=1, full1=2, empty0=3, empty1=4, producers-only=5
    if (wid < 8) {
        // ================= producers: GEMM =================
        const int mg = wid & 3, hh = wid >> 2;
        const unsigned aoff = (unsigned)((lane & 15) * 272 + (lane >> 4) * 16);
        const unsigned boff = (unsigned)(((((lane >> 3) & 1) * 8) + (lane & 7)) * 208);
        const unsigned bHi0 = smem_u32 + (unsigned)BHI_B + (unsigned)(hh * 112) + boff;
        const unsigned bLo0 = smem_u32 + (unsigned)BLO_B + (unsigned)(hh * 112) + boff;

        for (int g = 0; g < 16; g++) {
            const int c = g >> 1, h = g & 1, buf = g & 1;
            if (h == 0 && c > 0) {       // B(c) staged by all producers?
                cp_wait0();
                bar_sync_cnt(5, 256);
            }
            if (g >= 2) bar_sync_cnt(3 + buf, 512);   // raw[buf] free

            float acc[7][4];
            #pragma unroll
            for (int nt = 0; nt < 7; nt++)
                #pragma unroll
                for (int q = 0; q < 4; q++) acc[nt][q] = 0.f;

            const unsigned aHi0 = smem_u32 + (unsigned)AHI_B
                                  + (unsigned)((h * 64 + mg * 16) * 272) + aoff;
            const unsigned aLo0 = smem_u32 + (unsigned)ALO_B
                                  + (unsigned)((h * 64 + mg * 16) * 272) + aoff;

            #pragma unroll
            for (int ks = 0; ks < 8; ks++) {
                unsigned ah[4], al[4];
                ldsm_x4(aHi0 + (unsigned)(ks * 32), ah[0], ah[1], ah[2], ah[3]);
                ldsm_x4(aLo0 + (unsigned)(ks * 32), al[0], al[1], al[2], al[3]);
                #pragma unroll
                for (int nt = 0; nt < 7; nt++) {
                    if (hh == 1 && nt == 6) continue;   // cols >= 104
                    unsigned b0, b1, c0, c1;
                    ldsm_x2t(bHi0 + (unsigned)(ks * 3328 + nt * 16), b0, b1);
                    ldsm_x2t(bLo0 + (unsigned)(ks * 3328 + nt * 16), c0, c1);
                    mma16816(acc[nt], ah, b0, b1);   // Ahi*Bhi
                    mma16816(acc[nt], al, b0, b1);   // Alo*Bhi
                    mma16816(acc[nt], ah, c0, c1);   // Ahi*Blo
                }
            }
            // D fragments -> raw[buf] (64 rows x stride 105)
            float* raw = reinterpret_cast<float*>(smc + RAW_B + buf * 26880);
            #pragma unroll
            for (int nt = 0; nt < 7; nt++) {
                int col = hh * 56 + nt * 8 + 2 * (lane & 3);
                if (col < 100) {
                    int rl = mg * 16 + (lane >> 2);
                    raw[rl * 105 + col]           = acc[nt][0];
                    raw[rl * 105 + col + 1]       = acc[nt][1];
                    raw[(rl + 8) * 105 + col]     = acc[nt][2];
                    raw[(rl + 8) * 105 + col + 1] = acc[nt][3];
                }
            }
            bar_arrive512(1 + buf);      // raw[buf] full

            if (h == 1 && c < 7) {
                bar_sync_cnt(5, 256);    // all producers done reading B(c)
                const char* srcH = reinterpret_cast<const char*>(gWpHi)
                                   + (size_t)(c + 1) * 26624;
                const char* srcL = reinterpret_cast<const char*>(gWpLo)
                                   + (size_t)(c + 1) * 26624;
                const int ptid = tid;    // 0..255
                #pragma unroll
                for (int i = ptid; i < 1664; i += 256) {
                    cp_async16(smem_u32 + (unsigned)(BHI_B + i * 16), srcH + i * 16);
                    cp_async16(smem_u32 + (unsigned)(BLO_B + i * 16), srcL + i * 16);
                }
                cp_commit();
            }
        }
    } else {
        // ================= consumers: spline epilogue =================
        const int ct = tid - 256;
        const int rl = ct >> 2, eq = ct & 3;
        float ldh0 = 0.f, ldh1 = 0.f;
        for (int g = 0; g < 16; g++) {
            const int c = g >> 1, h = g & 1, buf = g & 1;
            bar_sync_cnt(1 + buf, 512);              // raw[buf] full
            const float* rawp = reinterpret_cast<const float*>(smc + RAW_B + buf * 26880)
                                + rl * 105 + eq * 25;
            float ld = rqs_epilogue(rawp, sBP + (c * 4 + eq) * 25,
                                    sXU + (h * 64 + rl) * 33 + c * 4 + eq);
            if (h == 0) ldh0 += ld; else ldh1 += ld;
            bar_arrive512(3 + buf);                  // raw[buf] free
        }
        // log_det: reduce over the 4 dim-threads of each row
        ldh0 += __shfl_xor_sync(0xffffffffu, ldh0, 1);
        ldh0 += __shfl_xor_sync(0xffffffffu, ldh0, 2);
        ldh1 += __shfl_xor_sync(0xffffffffu, ldh1, 1);
        ldh1 += __shfl_xor_sync(0xffffffffu, ldh1, 2);
        if (eq == 0) {
            out[(size_t)kB * 64 + r0 + rl]      = ldh0;
            out[(size_t)kB * 64 + r0 + 64 + rl] = ldh1;
        }
    }
    __syncthreads();

    // final y: re-read x for xm, interleave with yu; float4 coalesced
    {
        const float4* xg = reinterpret_cast<const float4*>(x + (size_t)r0 * 64);
        float4* og = reinterpret_cast<float4*>(out + (size_t)r0 * 64);
        #pragma unroll
        for (int i = tid; i < 128 * 16; i += kThreads) {
            int r = i >> 4, v = i & 15;
            float4 f = xg[i];
            og[i] = make_float4(f.x, sXU[r * 33 + 2 * v],
                                f.z, sXU[r * 33 + 2 * v + 1]);
        }
    }
}

extern "C" void kernel_launch(void* const* d_in, const int* in_sizes, int n_in,
                              void* d_out, int out_size)
{
    (void)in_sizes; (void)n_in; (void)out_size;
    const float* x   = (const float*)d_in[0];
    const float* W0  = (const float*)d_in[1];
    const float* b0  = (const float*)d_in[2];
    const float* g0  = (const float*)d_in[3];
    const float* be0 = (const float*)d_in[4];
    const float* W1  = (const float*)d_in[5];
    const float* b1  = (const float*)d_in[6];
    const float* g1  = (const float*)d_in[7];
    const float* be1 = (const float*)d_in[8];
    const float* Wp  = (const float*)d_in[9];
    const float* bp  = (const float*)d_in[10];
    float* out = (float*)d_out;

    prep_wp_kernel<<<(8 * 128 * 104 + 255) / 256, 256>>>(Wp);

    cudaFuncSetAttribute(spline_fused_kernel,
                         cudaFuncAttributeMaxDynamicSharedMemorySize, SMEM_BYTES);
    spline_fused_kernel<<<kB / 128, kThreads, SMEM_BYTES>>>(
        x, W0, b0, g0, be0, W1, b1, g1, be1, Wp, bp, out);
}

// round 17
// speedup vs baseline: 1.5443x; 1.5443x over previous
#include <cuda_runtime.h>
#include <cuda_bf16.h>

// ----------------------------------------------------------------------------
// SplineCoupling fused kernel, round 17: R15 with the cp.async publish race
// fixed (wait_group BEFORE the barrier that precedes cross-thread reads).
// GEMM3 on mma.sync.m16n8k16 bf16 (2-term split, merged k-loop), 16 GEMM
// warps, phases 1-2 FFMA, Wp pre-split by a prep kernel. ~196KB smem.
// ----------------------------------------------------------------------------

namespace {
constexpr int kB       = 262144;
constexpr int kThreads = 512;

// byte offsets in dynamic smem
constexpr int XU_B  = 0;        // 16896 : xu -> yu (128*33 f32)
constexpr int BP_B  = 16896;    // 3200  : bp
constexpr int BV_B  = 20096;    // 3072  : b0,g0,be0,b1,g1,be1
constexpr int AHI_B = 23168;    // 34816 : A_hi bf16 [m][k] stride 272B
constexpr int ALO_B = 57984;    // 34816 : A_lo
constexpr int BHI_B = 92800;    // 26624 : B_hi bf16 [k][104] stride 208B
constexpr int BLO_B = 119424;   // 26624 : B_lo
constexpr int RAW_B = 146048;   // 53760 : raw logits f32 [row][105]
constexpr int SMEM_BYTES = 199808;
// phase 1-2 overlays
constexpr int W_B  = AHI_B;     // W0 (16KB) then W1 (64KB) fp32
constexpr int XM_B = BHI_B;     // xm 128*33 f32
constexpr int H1_B = 109696;    // H1 128*129 f32 (dead before stage_b(0))
}  // namespace

__device__ __align__(16) __nv_bfloat16 gWpHi[8 * 128 * 104];
__device__ __align__(16) __nv_bfloat16 gWpLo[8 * 128 * 104];

__global__ void prep_wp_kernel(const float* __restrict__ Wp) {
    int idx = blockIdx.x * blockDim.x + threadIdx.x;
    if (idx >= 8 * 128 * 104) return;
    int c = idx / (128 * 104);
    int rem = idx - c * 128 * 104;
    int k = rem / 104, n = rem - k * 104;
    float v = (n < 100) ? Wp[k * 800 + c * 100 + n] : 0.f;
    __nv_bfloat16 hi = __float2bfloat16(v);
    __nv_bfloat16 lo = __float2bfloat16(v - __bfloat162float(hi));
    gWpHi[idx] = hi;
    gWpLo[idx] = lo;
}

__device__ __forceinline__ void cp_async16(unsigned dst, const void* src) {
    asm volatile("cp.async.cg.shared.global [%0], [%1], 16;" :: "r"(dst), "l"(src));
}
__device__ __forceinline__ void cp_commit() { asm volatile("cp.async.commit_group;"); }
__device__ __forceinline__ void cp_wait0()  { asm volatile("cp.async.wait_group 0;"); }

__device__ __forceinline__ void ldsm_x4(unsigned addr, unsigned& r0, unsigned& r1,
                                        unsigned& r2, unsigned& r3) {
    asm volatile("ldmatrix.sync.aligned.m8n8.x4.shared.b16 {%0,%1,%2,%3}, [%4];"
                 : "=r"(r0), "=r"(r1), "=r"(r2), "=r"(r3) : "r"(addr));
}
__device__ __forceinline__ void ldsm_x2t(unsigned addr, unsigned& r0, unsigned& r1) {
    asm volatile("ldmatrix.sync.aligned.m8n8.x2.trans.shared.b16 {%0,%1}, [%2];"
                 : "=r"(r0), "=r"(r1) : "r"(addr));
}
__device__ __forceinline__ void mma16816(float* d, const unsigned* a,
                                         unsigned b0, unsigned b1) {
    asm volatile(
        "mma.sync.aligned.m16n8k16.row.col.f32.bf16.bf16.f32 "
        "{%0,%1,%2,%3}, {%4,%5,%6,%7}, {%8,%9}, {%0,%1,%2,%3};"
        : "+f"(d[0]), "+f"(d[1]), "+f"(d[2]), "+f"(d[3])
        : "r"(a[0]), "r"(a[1]), "r"(a[2]), "r"(a[3]), "r"(b0), "r"(b1));
}

// RQS spline epilogue for one (row, dim): proven numerics since R6.
__device__ __forceinline__ float rqs_epilogue(const float* __restrict__ rawp,
                                              const float* __restrict__ bpd,
                                              float* __restrict__ xuslot)
{
    float wr[8], hr[8], dr9[9];
    #pragma unroll
    for (int j = 0; j < 8; j++) wr[j] = rawp[j] + bpd[j];
    #pragma unroll
    for (int j = 0; j < 8; j++) hr[j] = rawp[8 + j] + bpd[8 + j];
    #pragma unroll
    for (int j = 0; j < 9; j++) dr9[j] = rawp[16 + j] + bpd[16 + j];

    float mw = wr[0];
    #pragma unroll
    for (int j = 1; j < 8; j++) mw = fmaxf(mw, wr[j]);
    float ew[8], sw = 0.f;
    #pragma unroll
    for (int j = 0; j < 8; j++) { ew[j] = __expf(wr[j] - mw); sw += ew[j]; }
    float scw = 5.952f / sw;
    float w[8];
    #pragma unroll
    for (int j = 0; j < 8; j++) w[j] = 0.006f + ew[j] * scw;

    float mh = hr[0];
    #pragma unroll
    for (int j = 1; j < 8; j++) mh = fmaxf(mh, hr[j]);
    float eh[8], shs = 0.f;
    #pragma unroll
    for (int j = 0; j < 8; j++) { eh[j] = __expf(hr[j] - mh); shs += eh[j]; }
    float sch = 5.952f / shs;
    float h[8];
    #pragma unroll
    for (int j = 0; j < 8; j++) h[j] = 0.006f + eh[j] * sch;

    float dv[9];
    #pragma unroll
    for (int j = 0; j < 9; j++) {
        float xx = dr9[j];
        dv[j] = fmaxf(xx, 0.f) + __logf(1.f + __expf(-fabsf(xx))) + 0.001f;
    }

    float xu = *xuslot;
    bool inside = (xu > -3.f) && (xu < 3.f);
    float xc = fminf(fmaxf(xu, -3.f), 3.f);

    float cwv[9], chv[9];
    cwv[0] = -3.f; chv[0] = -3.f;
    #pragma unroll
    for (int j = 0; j < 8; j++) {
        cwv[j + 1] = cwv[j] + w[j];
        chv[j + 1] = chv[j] + h[j];
    }
    int idx = 0;
    #pragma unroll
    for (int j = 1; j <= 8; j++) idx += (xc >= cwv[j]) ? 1 : 0;
    idx = min(idx, 7);

    float w_k = w[0], x_k = cwv[0], h_k = h[0], y_k = chv[0];
    float d_k = dv[0], d_k1 = dv[1];
    #pragma unroll
    for (int j = 1; j < 8; j++) {
        if (idx == j) {
            w_k = w[j]; x_k = cwv[j]; h_k = h[j]; y_k = chv[j];
            d_k = dv[j]; d_k1 = dv[j + 1];
        }
    }
    float s   = h_k / w_k;
    float th  = (xc - x_k) / w_k;
    float om  = 1.f - th;
    float t1m = th * om;
    float den = s + (d_k1 + d_k - 2.f * s) * t1m;
    float yin = y_k + h_k * (s * th * th + d_k * t1m) / den;
    float num = d_k1 * th * th + 2.f * s * t1m + d_k * om * om;
    float ldin = 2.f * __logf(s) + __logf(num) - 2.f * __logf(den);

    *xuslot = inside ? yin : xu;
    return inside ? ldin : 0.f;
}

__global__ void __launch_bounds__(512, 1) spline_fused_kernel(
    const float* __restrict__ x,
    const float* __restrict__ W0, const float* __restrict__ b0,
    const float* __restrict__ g0, const float* __restrict__ be0,
    const float* __restrict__ W1, const float* __restrict__ b1,
    const float* __restrict__ g1, const float* __restrict__ be1,
    const float* __restrict__ Wp, const float* __restrict__ bp,
    float* __restrict__ out)
{
    extern __shared__ char smc[];
    float* sXU  = reinterpret_cast<float*>(smc + XU_B);
    float* sBP  = reinterpret_cast<float*>(smc + BP_B);
    float* sBV  = reinterpret_cast<float*>(smc + BV_B);
    float* sW   = reinterpret_cast<float*>(smc + W_B);    // W0 -> W1 (fp32)
    float* sXM  = reinterpret_cast<float*>(smc + XM_B);   // xm
    float* sH1  = reinterpret_cast<float*>(smc + H1_B);   // H1
    float* sRaw = reinterpret_cast<float*>(smc + RAW_B);
    const unsigned smem_u32 = (unsigned)__cvta_generic_to_shared(smc);

    const int tid  = threadIdx.x;
    const int wid  = tid >> 5;
    const int lane = tid & 31;
    const int r0   = blockIdx.x * 128;

    // ---------------- cooperative loads ----------------
    {
        const float4* xg = reinterpret_cast<const float4*>(x + (size_t)r0 * 64);
        #pragma unroll
        for (int i = tid; i < 128 * 16; i += kThreads) {
            int r = i >> 4, v = i & 15;
            float4 f = xg[i];
            sXM[r * 33 + 2 * v]     = f.x;
            sXU[r * 33 + 2 * v]     = f.y;
            sXM[r * 33 + 2 * v + 1] = f.z;
            sXU[r * 33 + 2 * v + 1] = f.w;
        }
        const float4* w0g = reinterpret_cast<const float4*>(W0);
        #pragma unroll
        for (int i = tid; i < 1024; i += kThreads)
            reinterpret_cast<float4*>(sW)[i] = w0g[i];
        const float4* bpg = reinterpret_cast<const float4*>(bp);
        #pragma unroll
        for (int i = tid; i < 200; i += kThreads)
            reinterpret_cast<float4*>(sBP)[i] = bpg[i];
        if (tid < 128) {
            sBV[tid]       = b0[tid];
            sBV[128 + tid] = g0[tid];
            sBV[256 + tid] = be0[tid];
            sBV[384 + tid] = b1[tid];
            sBV[512 + tid] = g1[tid];
            sBV[640 + tid] = be1[tid];
        }
    }
    __syncthreads();

    // ---------------- Phase 1: GEMM1 (K=32) tile 4x8 ----------------
    {
        const int rg = tid >> 4, cg = tid & 15;
        float acc1[4][8];
        #pragma unroll
        for (int r = 0; r < 4; r++)
            #pragma unroll
            for (int i = 0; i < 8; i++) acc1[r][i] = 0.f;

        #pragma unroll 4
        for (int k = 0; k < 32; k++) {
            float a[4];
            #pragma unroll
            for (int r = 0; r < 4; r++) a[r] = sXM[(rg * 4 + r) * 33 + k];
            #pragma unroll
            for (int i = 0; i < 8; i++) {
                float b = sW[k * 128 + cg + 16 * i];
                #pragma unroll
                for (int r = 0; r < 4; r++) acc1[r][i] += a[r] * b;
            }
        }
        __syncthreads();   // W0 reads done

        {   // kick W1 into sW via cp.async
            const float4* w1g = reinterpret_cast<const float4*>(W1);
            #pragma unroll
            for (int i = tid; i < 4096; i += kThreads)
                cp_async16(smem_u32 + (unsigned)(W_B + i * 16), w1g + i);
            cp_commit();
        }

        float mu[4], rs[4];
        #pragma unroll
        for (int r = 0; r < 4; r++) {
            float s1 = 0.f, s2 = 0.f;
            #pragma unroll
            for (int i = 0; i < 8; i++) {
                float v = acc1[r][i] + sBV[cg + 16 * i];
                acc1[r][i] = v;
                s1 += v; s2 += v * v;
            }
            #pragma unroll
            for (int d = 1; d < 16; d <<= 1) {
                s1 += __shfl_xor_sync(0xffffffffu, s1, d);
                s2 += __shfl_xor_sync(0xffffffffu, s2, d);
            }
            mu[r] = s1 * (1.f / 128.f);
            rs[r] = rsqrtf(s2 * (1.f / 128.f) - mu[r] * mu[r] + 1e-6f);
        }
        #pragma unroll
        for (int i = 0; i < 8; i++) {
            int c = cg + 16 * i;
            float gg = sBV[128 + c], bb = sBV[256 + c];
            #pragma unroll
            for (int r = 0; r < 4; r++) {
                float h = (acc1[r][i] - mu[r]) * rs[r] * gg + bb;
                sH1[(rg * 4 + r) * 129 + c] = fmaxf(h, 0.f);
            }
        }
    }
    cp_wait0();
    __syncthreads();

    // ---------------- Phase 2: GEMM2 (K=128) tile 8x8, 256 threads ---------
    {
        const bool p2  = tid < 256;
        const int rg2  = tid >> 4;
        const int cg2  = tid & 15;
        float a2[8][8];
        if (p2) {
            #pragma unroll
            for (int r = 0; r < 8; r++)
                #pragma unroll
                for (int j = 0; j < 8; j++) a2[r][j] = 0.f;

            #pragma unroll 2
            for (int k = 0; k < 128; k++) {
                float bv_[8];
                #pragma unroll
                for (int j = 0; j < 8; j++) bv_[j] = sW[k * 128 + 16 * j + cg2];
                #pragma unroll
                for (int r = 0; r < 8; r++) {
                    float av = sH1[(rg2 * 8 + r) * 129 + k];
                    #pragma unroll
                    for (int j = 0; j < 8; j++) a2[r][j] += av * bv_[j];
                }
            }
            #pragma unroll
            for (int r = 0; r < 8; r++) {
                float s1 = 0.f, s2 = 0.f;
                #pragma unroll
                for (int j = 0; j < 8; j++) {
                    float v = a2[r][j] + sBV[384 + 16 * j + cg2];
                    a2[r][j] = v;
                    s1 += v; s2 += v * v;
                }
                #pragma unroll
                for (int d = 1; d < 16; d <<= 1) {
                    s1 += __shfl_xor_sync(0xffffffffu, s1, d);
                    s2 += __shfl_xor_sync(0xffffffffu, s2, d);
                }
                float mu = s1 * (1.f / 128.f);
                float rs = rsqrtf(s2 * (1.f / 128.f) - mu * mu + 1e-6f);
                #pragma unroll
                for (int j = 0; j < 8; j++) {
                    int c = 16 * j + cg2;
                    float h = fmaxf((a2[r][j] - mu) * rs * sBV[512 + c] + sBV[640 + c], 0.f)
                              + sH1[(rg2 * 8 + r) * 129 + c];   // residual
                    a2[r][j] = h;
                }
            }
        }
        __syncthreads();   // all W1 + H1 reads complete (uniform barrier)
        if (p2) {
            // H2 -> A_hi/A_lo bf16, [m][k] row-major stride 272B
            #pragma unroll
            for (int r = 0; r < 8; r++) {
                int m = rg2 * 8 + r;
                #pragma unroll
                for (int j = 0; j < 8; j++) {
                    int k = 16 * j + cg2;
                    float v = a2[r][j];
                    __nv_bfloat16 hi = __float2bfloat16(v);
                    __nv_bfloat16 lo = __float2bfloat16(v - __bfloat162float(hi));
                    *reinterpret_cast<unsigned short*>(smc + AHI_B + m * 272 + k * 2) =
                        __bfloat16_as_ushort(hi);
                    *reinterpret_cast<unsigned short*>(smc + ALO_B + m * 272 + k * 2) =
                        __bfloat16_as_ushort(lo);
                }
            }
        }
    }

    // ---------------- Phase 3: 8 chunks of 100 cols, mma.sync --------------
    // stage chunk c from pre-split globals: pure cp.async, 26624B per buffer
    auto stage_b = [&](int c) {
        const char* srcH = reinterpret_cast<const char*>(gWpHi) + (size_t)c * 26624;
        const char* srcL = reinterpret_cast<const char*>(gWpLo) + (size_t)c * 26624;
        #pragma unroll
        for (int i = tid; i < 1664; i += kThreads) {
            cp_async16(smem_u32 + (unsigned)(BHI_B + i * 16), srcH + i * 16);
            cp_async16(smem_u32 + (unsigned)(BLO_B + i * 16), srcL + i * 16);
        }
        cp_commit();
    };
    stage_b(0);
    cp_wait0();        // own copies done...
    __syncthreads();   // ...and published to all threads (A-split stores too)

    // ldmatrix lane offsets (bytes); A tile = 16 rows x 16 cols per ldsm_x4
    const unsigned aoff = (unsigned)((lane & 15) * 272 + (lane >> 4) * 16);
    const unsigned boff = (unsigned)(((((lane >> 3) & 1) * 8) + (lane & 7)) * 208);
    const int mg = wid & 7, hh = wid >> 3;    // 16 GEMM warps: 8 m-tiles x 2 n-halves
    const int erow = tid >> 2, eq = tid & 3;
    float ld_acc = 0.f;

    for (int c = 0; c < 8; c++) {
        {
            float acc[7][4];
            #pragma unroll
            for (int nt = 0; nt < 7; nt++)
                #pragma unroll
                for (int q = 0; q < 4; q++) acc[nt][q] = 0.f;

            const unsigned aHi0 = smem_u32 + AHI_B + (unsigned)(mg * 16) * 272u + aoff;
            const unsigned aLo0 = smem_u32 + ALO_B + (unsigned)(mg * 16) * 272u + aoff;
            const unsigned bHi0 = smem_u32 + BHI_B + (unsigned)(hh * 112) + boff;
            const unsigned bLo0 = smem_u32 + BLO_B + (unsigned)(hh * 112) + boff;

            // merged k-loop: per ks load Ahi/Alo once, apply Bhi and Blo
            #pragma unroll
            for (int ks = 0; ks < 8; ks++) {
                unsigned ah[4], al[4];
                ldsm_x4(aHi0 + (unsigned)(ks * 32), ah[0], ah[1], ah[2], ah[3]);
                ldsm_x4(aLo0 + (unsigned)(ks * 32), al[0], al[1], al[2], al[3]);
                #pragma unroll
                for (int nt = 0; nt < 7; nt++) {
                    if (hh == 1 && nt == 6) continue;      // cols >= 104
                    unsigned b0, b1, c0, c1;
                    ldsm_x2t(bHi0 + (unsigned)(ks * 3328 + nt * 16), b0, b1);
                    ldsm_x2t(bLo0 + (unsigned)(ks * 3328 + nt * 16), c0, c1);
                    mma16816(acc[nt], ah, b0, b1);   // Ahi * Bhi
                    mma16816(acc[nt], al, b0, b1);   // Alo * Bhi
                    mma16816(acc[nt], ah, c0, c1);   // Ahi * Blo
                }
            }
            // D fragments -> raw (stride 105)
            #pragma unroll
            for (int nt = 0; nt < 7; nt++) {
                int col = hh * 56 + nt * 8 + 2 * (lane & 3);
                if (col < 100) {
                    int row = mg * 16 + (lane >> 2);
                    sRaw[row * 105 + col]           = acc[nt][0];
                    sRaw[row * 105 + col + 1]       = acc[nt][1];
                    sRaw[(row + 8) * 105 + col]     = acc[nt][2];
                    sRaw[(row + 8) * 105 + col + 1] = acc[nt][3];
                }
            }
        }
        __syncthreads();   // raw complete; all B(c) reads done

        // issue next-chunk staging (async; latency hides under epilogue)
        if (c < 7) stage_b(c + 1);

        // spline epilogue (all 512 threads = 128 rows x 4 dims)
        ld_acc += rqs_epilogue(sRaw + erow * 105 + eq * 25,
                               sBP + (c * 4 + eq) * 25,
                               sXU + erow * 33 + c * 4 + eq);

        if (c < 7) cp_wait0();   // own B(c+1) copies complete...
        __syncthreads();         // ...published to all; raw free for next chunk
    }

    // log_det: reduce over the 4 dim-threads of each row
    ld_acc += __shfl_xor_sync(0xffffffffu, ld_acc, 1);
    ld_acc += __shfl_xor_sync(0xffffffffu, ld_acc, 2);
    if (eq == 0) out[(size_t)kB * 64 + r0 + erow] = ld_acc;

    // final y: re-read x for xm, interleave with yu; float4 coalesced
    {
        const float4* xg = reinterpret_cast<const float4*>(x + (size_t)r0 * 64);
        float4* og = reinterpret_cast<float4*>(out + (size_t)r0 * 64);
        #pragma unroll
        for (int i = tid; i < 128 * 16; i += kThreads) {
            int r = i >> 4, v = i & 15;
            float4 f = xg[i];
            og[i] = make_float4(f.x, sXU[r * 33 + 2 * v],
                                f.z, sXU[r * 33 + 2 * v + 1]);
        }
    }
}

extern "C" void kernel_launch(void* const* d_in, const int* in_sizes, int n_in,
                              void* d_out, int out_size)
{
    (void)in_sizes; (void)n_in; (void)out_size;
    const float* x   = (const float*)d_in[0];
    const float* W0  = (const float*)d_in[1];
    const float* b0  = (const float*)d_in[2];
    const float* g0  = (const float*)d_in[3];
    const float* be0 = (const float*)d_in[4];
    const float* W1  = (const float*)d_in[5];
    const float* b1  = (const float*)d_in[6];
    const float* g1  = (const float*)d_in[7];
    const float* be1 = (const float*)d_in[8];
    const float* Wp  = (const float*)d_in[9];
    const float* bp  = (const float*)d_in[10];
    float* out = (float*)d_out;

    prep_wp_kernel<<<(8 * 128 * 104 + 255) / 256, 256>>>(Wp);

    cudaFuncSetAttribute(spline_fused_kernel,
                         cudaFuncAttributeMaxDynamicSharedMemorySize, SMEM_BYTES);
    spline_fused_kernel<<<kB / 128, kThreads, SMEM_BYTES>>>(
        x, W0, b0, g0, be0, W1, b1, g1, be1, Wp, bp, out);
}